// round 7
// baseline (speedup 1.0000x reference)
#include <cuda_runtime.h>

#define IMG_H 1536
#define IMG_W 1536
#define NK 8
#define PW 7
#define NR 28      // CLIP_MAX+1 rows of F ever used
#define CLIPM 27

#define BS1 128
#define NCH 4                     // row chunks of 7
#define JB (IMG_W / BS1)          // 12 j-blocks
#define NBLK1 (NK * NCH * JB)     // 384 compute blocks; block NBLK1 = setup
#define NCLS 225                  // max distinct row classes: 1 + 8*28
#define NBLK3 (NCLS * 2)          // class x j-half

// Scratch (device globals only — no allocation allowed)
__device__ __align__(16) float g_F[NK * NR * IMG_W]; // thresholded F[k][row][j]
__device__ int      g_icount;
__device__ int      g_tapn[NCLS];                    // merged taps per class
__device__ int      g_taprow[NCLS * 32];             // row base offsets
__device__ float    g_tapw[NCLS * 32];               // merged weights
__device__ unsigned g_enc;                           // encoded running max
__device__ unsigned g_done;                          // completed geneo3 blocks

// Monotone float <-> uint encoding for atomicMax over signed floats.
__device__ __forceinline__ unsigned enc_f(float f) {
    int b = __float_as_int(f);
    return (b >= 0) ? ((unsigned)b | 0x80000000u) : ~(unsigned)b;
}
__device__ __forceinline__ float dec_f(unsigned u) {
    int b = (u & 0x80000000u) ? (int)(u ^ 0x80000000u) : ~(int)u;
    return __int_as_float(b);
}

// ---------------------------------------------------------------------------
// Kernel A: F[k,row,j] = 1 - (1/49) * sum_{a,b} |P[k,a,b] - pad[a+row, b+j]|
// Thread = (k, j); walks 7 output rows with a 7x7 register rolling window.
// Summation order is EXACTLY the reference's (a-major, b-minor, single chain)
// so F[k,0,0] == thr bitwise and no threshold flips are possible.
// Block NBLK1 = setup: row-class list + per-class merged tap tables + atomics.
// ---------------------------------------------------------------------------
__global__ void __launch_bounds__(BS1) geneo1_kernel(
        const float* __restrict__ x,
        const float* __restrict__ patterns,
        const float* __restrict__ vectors) {
    const int tid = threadIdx.x;

    if (blockIdx.x == NBLK1) {
        // ---- flag candidate i's, ordered warp-ballot compaction ----
        __shared__ unsigned char flags[IMG_W];
        __shared__ int s_ilist[NCLS];
        __shared__ int s_cnt;
        for (int i = tid; i < IMG_W; i += BS1) flags[i] = 0;
        __syncthreads();
        if (tid == 0) { flags[0] = 1; g_enc = 0u; g_done = 0u; }
        if (tid < NK * NR) {
            const int k = tid / NR, off = tid % NR;
            const int sy = (int)floorf(vectors[2 * k + 1]);
            const int i = sy + 1 + off;
            if (i >= 1 && i < IMG_W) flags[i] = 1;
        }
        __syncthreads();
        if (tid < 32) {
            int base = 0;
            for (int ch = 0; ch < IMG_W / 32; ch++) {
                const int f = flags[ch * 32 + tid];
                const unsigned m = __ballot_sync(0xffffffffu, f);
                if (f) s_ilist[base + __popc(m & ((1u << tid) - 1u))] = ch * 32 + tid;
                base += __popc(m);
            }
            if (tid == 0) { s_cnt = base; g_icount = base; }
        }
        __syncthreads();

        // ---- per-class merged tap tables (1 thread per class) ----
        const int cnt = s_cnt;
        for (int cls = tid; cls < cnt; cls += BS1) {
            const int i = s_ilist[cls];
            int   rows[32];
            float ws[32];
            int nt = 0;
            #pragma unroll
            for (int kk = 0; kk < NK; kk++) {
                const float v0 = vectors[2 * kk + 0];
                const float v1 = vectors[2 * kk + 1];
                const float fx = floorf(v0);
                const float fy = floorf(v1);
                const int   sx = (int)fx;
                const int   sy = (int)fy;
                const float px = fx - v0;
                const float py = fy - v1;
                const int nk0 = nt;                 // taps of this k start here
                #pragma unroll
                for (int c = 0; c < 4; c++) {
                    const int dx = c >> 1;          // corner order matches ref
                    const int dy = c & 1;
                    const float w = (dx ? (1.0f - px) : px) *
                                    (dy ? (1.0f - py) : py);
                    int t1 = i - (sy + dy);
                    t1 = min(max(t1, 0), CLIPM);
                    int r = t1 - (sx + dx);
                    r = min(max(r, 0), CLIPM);
                    const int base = (kk * NR + r) * IMG_W;
                    bool merged = false;
                    for (int t = nk0; t < nt; t++)
                        if (rows[t] == base) { ws[t] += w; merged = true; }
                    if (!merged) { rows[nt] = base; ws[nt] = w; nt++; }
                }
            }
            g_tapn[cls] = nt;
            for (int t = 0; t < nt; t++) {
                g_taprow[cls * 32 + t] = rows[t];
                g_tapw[cls * 32 + t]   = ws[t];
            }
        }
        return;
    }

    const int k   = blockIdx.x / (NCH * JB);
    const int rem = blockIdx.x % (NCH * JB);
    const int r0  = (rem / JB) * 7;               // first output row of chunk
    const int j   = (rem % JB) * BS1 + tid;

    // Pattern in registers.
    float p[PW * PW];
    #pragma unroll
    for (int t = 0; t < PW * PW; t++) p[t] = __ldg(&patterns[k * PW * PW + t]);

    // thr = F_raw(0,0): window all zeros there; same sequential order.
    float s = 0.0f;
    #pragma unroll
    for (int t = 0; t < PW * PW; t++) s += fabsf(p[t]);
    const float thr = 1.0f - s * (1.0f / 49.0f);

    // Initial window: x rows r0-7 .. r0-1, cols j-7 .. j-1 (j-7+b).
    float win[PW][PW];
    #pragma unroll
    for (int a = 0; a < PW; a++) {
        const int r = r0 - PW + a;
        #pragma unroll
        for (int b = 0; b < PW; b++) {
            const int c = j - PW + b;
            win[a][b] = (r >= 0 && c >= 0) ? __ldg(&x[r * IMG_W + c]) : 0.0f;
        }
    }

    #pragma unroll
    for (int step = 0; step < PW; step++) {
        const int row = r0 + step;
        float acc = 0.0f;
        #pragma unroll
        for (int a = 0; a < PW; a++)
            #pragma unroll
            for (int b = 0; b < PW; b++)
                acc += fabsf(p[a * PW + b] - win[a][b]);
        const float f = 1.0f - acc * (1.0f / 49.0f);
        g_F[(k * NR + row) * IMG_W + j] = (f > thr) ? f : 0.0f;

        if (step < PW - 1) {
            #pragma unroll
            for (int a = 0; a < PW - 1; a++)
                #pragma unroll
                for (int b = 0; b < PW; b++)
                    win[a][b] = win[a + 1][b];
            #pragma unroll
            for (int b = 0; b < PW; b++) {
                const int c = j - PW + b;           // row 'row' is always >= 0
                win[PW - 1][b] = (c >= 0) ? __ldg(&x[row * IMG_W + c]) : 0.0f;
            }
        }
    }
}

// ---------------------------------------------------------------------------
// Kernel B: block = (class, j-half). Tap tables are precomputed; the block
// just issues up to 32 independent float2 gathers (full MLP, one exposed L2
// latency), reduces, and feeds the fused global max.
// ---------------------------------------------------------------------------
__global__ void __launch_bounds__(384, 2) geneo3_kernel(
        float* __restrict__ out) {
    const int cls  = blockIdx.x >> 1;
    const int half = blockIdx.x & 1;
    const int tid  = threadIdx.x;
    __shared__ float smax[12];

    const int  count  = __ldg(&g_icount);
    const bool active = (cls < count);
    float m = -3.0e38f;

    if (active) {
        const int ntap = __ldg(&g_tapn[cls]);
        const int joff = half * (IMG_W / 2) + 2 * tid;
        float2 acc = make_float2(0.f, 0.f);
        #pragma unroll
        for (int t = 0; t < 32; t++) {
            if (t < ntap) {
                const float  w = __ldg(&g_tapw[cls * 32 + t]);
                const int    r = __ldg(&g_taprow[cls * 32 + t]);
                const float2 v = *(const float2*)&g_F[r + joff];
                acc.x = fmaf(w, v.x, acc.x);
                acc.y = fmaf(w, v.y, acc.y);
            }
        }
        m = fmaxf(acc.x, acc.y);

        #pragma unroll
        for (int o = 16; o > 0; o >>= 1)
            m = fmaxf(m, __shfl_xor_sync(0xffffffffu, m, o));
        if ((tid & 31) == 0) smax[tid >> 5] = m;
        __syncthreads();
        if (tid == 0) {
            #pragma unroll
            for (int w = 1; w < 12; w++) m = fmaxf(m, smax[w]);
        }
    }

    if (tid == 0) {
        if (active) atomicMax(&g_enc, enc_f(m));
        __threadfence();
        const unsigned old = atomicAdd(&g_done, 1u);
        if (old == (unsigned)(NBLK3 - 1)) {
            const unsigned u = atomicOr(&g_enc, 0u);   // coherent read
            out[0] = dec_f(u) * (1.0f / 7.0f);
        }
    }
}

extern "C" void kernel_launch(void* const* d_in, const int* in_sizes, int n_in,
                              void* d_out, int out_size) {
    const float* x        = (const float*)d_in[0];
    const float* patterns = (const float*)d_in[1];
    const float* vectors  = (const float*)d_in[2];
    float* out = (float*)d_out;

    geneo1_kernel<<<NBLK1 + 1, BS1>>>(x, patterns, vectors);
    geneo3_kernel<<<NBLK3, 384>>>(out);
}

// round 10
// speedup vs baseline: 1.3271x; 1.3271x over previous
#include <cuda_runtime.h>

#define IMG_H 1536
#define IMG_W 1536
#define NK 8
#define PW 7
#define NR 28      // CLIP_MAX+1 rows of F ever used
#define CLIPM 27

#define BS1 128
#define NCH 4                     // row chunks of 7
#define JB (IMG_W / BS1)          // 12 j-blocks
#define NBLK1 (NK * NCH * JB)     // 384 compute blocks; block NBLK1 = setup
#define NCLS 225                  // max distinct row classes: 1 + 8*28

#define TC 16                     // columns per geneo3 block
#define NBLK3 (IMG_W / TC)        // 96 blocks, one wave
#define SPAD 17                   // padded smem row stride (bank spread)
#define NGRP 24                   // class groups per block (384/16)
#define NIT  10                   // ceil(225/24)

// Scratch (device globals only — no allocation allowed)
__device__ __align__(16) float g_F[NK * NR * IMG_W]; // thresholded F[k][row][j]
__device__ int      g_icount;
__device__ int2     g_tap[NCLS * 32];  // .x = smem row offset (row*SPAD), .y = weight bits
__device__ unsigned g_enc;             // encoded running max
__device__ unsigned g_done;            // completed geneo3 blocks

// Monotone float <-> uint encoding for atomicMax over signed floats.
__device__ __forceinline__ unsigned enc_f(float f) {
    int b = __float_as_int(f);
    return (b >= 0) ? ((unsigned)b | 0x80000000u) : ~(unsigned)b;
}
__device__ __forceinline__ float dec_f(unsigned u) {
    int b = (u & 0x80000000u) ? (int)(u ^ 0x80000000u) : ~(int)u;
    return __int_as_float(b);
}

// ---------------------------------------------------------------------------
// Kernel A: F[k,row,j] = 1 - (1/49) * sum_{a,b} |P[k,a,b] - pad[a+row, b+j]|
// Thread = (k, j); walks 7 output rows with a 7x7 register rolling window.
// Summation order is EXACTLY the reference's (a-major, b-minor, single chain)
// so F[k,0,0] == thr bitwise and no threshold flips are possible.
// Block NBLK1 = setup: class list + UNMERGED tap table (7200 independent
// entries, no local arrays, no spills) + atomics reset.
// ---------------------------------------------------------------------------
__global__ void __launch_bounds__(BS1) geneo1_kernel(
        const float* __restrict__ x,
        const float* __restrict__ patterns,
        const float* __restrict__ vectors) {
    const int tid = threadIdx.x;

    if (blockIdx.x == NBLK1) {
        // ---- flag candidate i's, ordered warp-ballot compaction ----
        __shared__ unsigned char flags[IMG_W];
        __shared__ int s_ilist[NCLS];
        __shared__ int s_cnt;
        for (int i = tid; i < IMG_W; i += BS1) flags[i] = 0;
        __syncthreads();
        if (tid == 0) { flags[0] = 1; g_enc = 0u; g_done = 0u; }
        if (tid < NK * NR) {
            const int k = tid / NR, off = tid % NR;
            const int sy = (int)floorf(vectors[2 * k + 1]);
            const int i = sy + 1 + off;
            if (i >= 1 && i < IMG_W) flags[i] = 1;
        }
        __syncthreads();
        if (tid < 32) {
            int base = 0;
            for (int ch = 0; ch < IMG_W / 32; ch++) {
                const int f = flags[ch * 32 + tid];
                const unsigned m = __ballot_sync(0xffffffffu, f);
                if (f) s_ilist[base + __popc(m & ((1u << tid) - 1u))] = ch * 32 + tid;
                base += __popc(m);
            }
            if (tid == 0) { s_cnt = base; g_icount = base; }
        }
        __syncthreads();

        // ---- unmerged tap table: entry e = (class, tap) fully independent ----
        const int cnt = s_cnt;
        for (int e = tid; e < cnt * 32; e += BS1) {
            const int cls = e >> 5;
            const int t   = e & 31;
            const int i   = s_ilist[cls];
            const int kk  = t >> 2;
            const int c   = t & 3;
            const float v0 = __ldg(&vectors[2 * kk + 0]);
            const float v1 = __ldg(&vectors[2 * kk + 1]);
            const float fx = floorf(v0);
            const float fy = floorf(v1);
            const int   sx = (int)fx;
            const int   sy = (int)fy;
            const float px = fx - v0;
            const float py = fy - v1;
            const int dx = c >> 1;          // corner order matches reference
            const int dy = c & 1;
            const float w = (dx ? (1.0f - px) : px) * (dy ? (1.0f - py) : py);
            int t1 = i - (sy + dy);
            t1 = min(max(t1, 0), CLIPM);
            int r = t1 - (sx + dx);
            r = min(max(r, 0), CLIPM);
            g_tap[e] = make_int2((kk * NR + r) * SPAD, __float_as_int(w));
        }
        return;
    }

    const int k   = blockIdx.x / (NCH * JB);
    const int rem = blockIdx.x % (NCH * JB);
    const int r0  = (rem / JB) * 7;               // first output row of chunk
    const int j   = (rem % JB) * BS1 + tid;

    // Pattern in registers.
    float p[PW * PW];
    #pragma unroll
    for (int t = 0; t < PW * PW; t++) p[t] = __ldg(&patterns[k * PW * PW + t]);

    // thr = F_raw(0,0): window all zeros there; same sequential order.
    float s = 0.0f;
    #pragma unroll
    for (int t = 0; t < PW * PW; t++) s += fabsf(p[t]);
    const float thr = 1.0f - s * (1.0f / 49.0f);

    // Initial window: x rows r0-7 .. r0-1, cols j-7 .. j-1 (j-7+b).
    float win[PW][PW];
    #pragma unroll
    for (int a = 0; a < PW; a++) {
        const int r = r0 - PW + a;
        #pragma unroll
        for (int b = 0; b < PW; b++) {
            const int c = j - PW + b;
            win[a][b] = (r >= 0 && c >= 0) ? __ldg(&x[r * IMG_W + c]) : 0.0f;
        }
    }

    #pragma unroll
    for (int step = 0; step < PW; step++) {
        const int row = r0 + step;
        float acc = 0.0f;
        #pragma unroll
        for (int a = 0; a < PW; a++)
            #pragma unroll
            for (int b = 0; b < PW; b++)
                acc += fabsf(p[a * PW + b] - win[a][b]);
        const float f = 1.0f - acc * (1.0f / 49.0f);
        g_F[(k * NR + row) * IMG_W + j] = (f > thr) ? f : 0.0f;

        if (step < PW - 1) {
            #pragma unroll
            for (int a = 0; a < PW - 1; a++)
                #pragma unroll
                for (int b = 0; b < PW; b++)
                    win[a][b] = win[a + 1][b];
            #pragma unroll
            for (int b = 0; b < PW; b++) {
                const int c = j - PW + b;           // row 'row' is always >= 0
                win[PW - 1][b] = (c >= 0) ? __ldg(&x[row * IMG_W + c]) : 0.0f;
            }
        }
    }
}

// ---------------------------------------------------------------------------
// Kernel B: 96 blocks, one per 16-column tile (single wave). Stage all 224
// F-rows for this tile into smem, then evaluate all 225 classes from smem:
// thread = (class-group, col); 32 taps of LDG.64 meta (L1-broadcast) +
// LDS + FMA. Block max -> one atomicMax; last block writes out.
// ---------------------------------------------------------------------------
__global__ void __launch_bounds__(384) geneo3_kernel(float* __restrict__ out) {
    __shared__ float sF[NK * NR * SPAD];
    __shared__ float smax[12];
    const int tid = threadIdx.x;
    const int j0  = blockIdx.x * TC;

    // Stage: 224 rows x 16 cols (float4 per thread-iteration).
    for (int e = tid; e < NK * NR * (TC / 4); e += 384) {
        const int row = e >> 2;
        const int q   = (e & 3) * 4;
        const float4 v = *(const float4*)&g_F[row * IMG_W + j0 + q];
        sF[row * SPAD + q + 0] = v.x;
        sF[row * SPAD + q + 1] = v.y;
        sF[row * SPAD + q + 2] = v.z;
        sF[row * SPAD + q + 3] = v.w;
    }
    __syncthreads();

    const int count = __ldg(&g_icount);
    const int col   = tid & (TC - 1);
    const int cgrp  = tid / TC;                // 0..23
    float m = -3.0e38f;

    #pragma unroll
    for (int it = 0; it < NIT; it++) {
        const int cls = cgrp + NGRP * it;
        if (cls < count) {
            const int2* tp = &g_tap[cls * 32];
            float acc = 0.0f;
            #pragma unroll
            for (int t = 0; t < 32; t++) {
                const int2 mt = __ldg(&tp[t]);
                acc = fmaf(__int_as_float(mt.y), sF[mt.x + col], acc);
            }
            m = fmaxf(m, acc);
        }
    }

    #pragma unroll
    for (int o = 16; o > 0; o >>= 1)
        m = fmaxf(m, __shfl_xor_sync(0xffffffffu, m, o));
    if ((tid & 31) == 0) smax[tid >> 5] = m;
    __syncthreads();
    if (tid == 0) {
        #pragma unroll
        for (int w = 1; w < 12; w++) m = fmaxf(m, smax[w]);
        atomicMax(&g_enc, enc_f(m));
        __threadfence();
        const unsigned old = atomicAdd(&g_done, 1u);
        if (old == (unsigned)(NBLK3 - 1)) {
            const unsigned u = atomicOr(&g_enc, 0u);   // coherent read
            out[0] = dec_f(u) * (1.0f / 7.0f);
        }
    }
}

extern "C" void kernel_launch(void* const* d_in, const int* in_sizes, int n_in,
                              void* d_out, int out_size) {
    const float* x        = (const float*)d_in[0];
    const float* patterns = (const float*)d_in[1];
    const float* vectors  = (const float*)d_in[2];
    float* out = (float*)d_out;

    geneo1_kernel<<<NBLK1 + 1, BS1>>>(x, patterns, vectors);
    geneo3_kernel<<<NBLK3, 384>>>(out);
}

// round 11
// speedup vs baseline: 1.4276x; 1.0757x over previous
#include <cuda_runtime.h>

#define IMG_H 1536
#define IMG_W 1536
#define NK 8
#define PW 7
#define NR 28      // CLIP_MAX+1 rows of F ever used
#define CLIPM 27

#define BS1 128
#define NCH 4                     // row chunks of 7
#define JB (IMG_W / BS1)          // 12 j-blocks
#define NBLK1 (NK * NCH * JB)     // 384 compute blocks; block NBLK1 = setup
#define NCLS 225                  // max distinct row classes: 1 + 8*28

#define TC 32                     // columns per geneo3 block tile
#define NSPLIT 3                  // class splits (cls mod 3)
#define NBLK3 ((IMG_W / TC) * NSPLIT)   // 48 * 3 = 144 blocks, ~one per SM
#define NROWS (NK * NR)           // 224
#define NGRP 48                   // class-groups per iteration (384/8)
#define NIT 2                     // 48*2 = 96 >= ceil(225/3)

// Scratch (device globals only — no allocation allowed)
__device__ __align__(16) float g_F[NROWS * IMG_W];  // thresholded F[k][row][j]
__device__ int      g_icount;
__device__ int2     g_tap[NCLS * 32];  // .x = row index (0..223), .y = weight bits
__device__ unsigned g_enc;             // encoded running max
__device__ unsigned g_done;            // completed geneo3 blocks

// Monotone float <-> uint encoding for atomicMax over signed floats.
__device__ __forceinline__ unsigned enc_f(float f) {
    int b = __float_as_int(f);
    return (b >= 0) ? ((unsigned)b | 0x80000000u) : ~(unsigned)b;
}
__device__ __forceinline__ float dec_f(unsigned u) {
    int b = (u & 0x80000000u) ? (int)(u ^ 0x80000000u) : ~(int)u;
    return __int_as_float(b);
}

// ---------------------------------------------------------------------------
// Kernel A: F[k,row,j] = 1 - (1/49) * sum_{a,b} |P[k,a,b] - pad[a+row, b+j]|
// Thread = (k, j); walks 7 output rows with a 7x7 register rolling window.
// Summation order is EXACTLY the reference's (a-major, b-minor, single chain)
// so F[k,0,0] == thr bitwise and no threshold flips are possible.
// Block NBLK1 = setup: class list + UNMERGED tap table (independent entries,
// no local arrays, no spills) + atomics reset.
// ---------------------------------------------------------------------------
__global__ void __launch_bounds__(BS1) geneo1_kernel(
        const float* __restrict__ x,
        const float* __restrict__ patterns,
        const float* __restrict__ vectors) {
    const int tid = threadIdx.x;

    if (blockIdx.x == NBLK1) {
        // ---- flag candidate i's, ordered warp-ballot compaction ----
        __shared__ unsigned char flags[IMG_W];
        __shared__ int s_ilist[NCLS];
        __shared__ int s_cnt;
        for (int i = tid; i < IMG_W; i += BS1) flags[i] = 0;
        __syncthreads();
        if (tid == 0) { flags[0] = 1; g_enc = 0u; g_done = 0u; }
        if (tid < NK * NR) {
            const int k = tid / NR, off = tid % NR;
            const int sy = (int)floorf(vectors[2 * k + 1]);
            const int i = sy + 1 + off;
            if (i >= 1 && i < IMG_W) flags[i] = 1;
        }
        __syncthreads();
        if (tid < 32) {
            int base = 0;
            for (int ch = 0; ch < IMG_W / 32; ch++) {
                const int f = flags[ch * 32 + tid];
                const unsigned m = __ballot_sync(0xffffffffu, f);
                if (f) s_ilist[base + __popc(m & ((1u << tid) - 1u))] = ch * 32 + tid;
                base += __popc(m);
            }
            if (tid == 0) { s_cnt = base; g_icount = base; }
        }
        __syncthreads();

        // ---- unmerged tap table: entry e = (class, tap) fully independent ----
        const int cnt = s_cnt;
        for (int e = tid; e < cnt * 32; e += BS1) {
            const int cls = e >> 5;
            const int t   = e & 31;
            const int i   = s_ilist[cls];
            const int kk  = t >> 2;
            const int c   = t & 3;
            const float v0 = __ldg(&vectors[2 * kk + 0]);
            const float v1 = __ldg(&vectors[2 * kk + 1]);
            const float fx = floorf(v0);
            const float fy = floorf(v1);
            const int   sx = (int)fx;
            const int   sy = (int)fy;
            const float px = fx - v0;
            const float py = fy - v1;
            const int dx = c >> 1;          // corner order matches reference
            const int dy = c & 1;
            const float w = (dx ? (1.0f - px) : px) * (dy ? (1.0f - py) : py);
            int t1 = i - (sy + dy);
            t1 = min(max(t1, 0), CLIPM);
            int r = t1 - (sx + dx);
            r = min(max(r, 0), CLIPM);
            g_tap[e] = make_int2(kk * NR + r, __float_as_int(w));
        }
        return;
    }

    const int k   = blockIdx.x / (NCH * JB);
    const int rem = blockIdx.x % (NCH * JB);
    const int r0  = (rem / JB) * 7;               // first output row of chunk
    const int j   = (rem % JB) * BS1 + tid;

    // Pattern in registers.
    float p[PW * PW];
    #pragma unroll
    for (int t = 0; t < PW * PW; t++) p[t] = __ldg(&patterns[k * PW * PW + t]);

    // thr = F_raw(0,0): window all zeros there; same sequential order.
    float s = 0.0f;
    #pragma unroll
    for (int t = 0; t < PW * PW; t++) s += fabsf(p[t]);
    const float thr = 1.0f - s * (1.0f / 49.0f);

    // Initial window: x rows r0-7 .. r0-1, cols j-7 .. j-1 (j-7+b).
    float win[PW][PW];
    #pragma unroll
    for (int a = 0; a < PW; a++) {
        const int r = r0 - PW + a;
        #pragma unroll
        for (int b = 0; b < PW; b++) {
            const int c = j - PW + b;
            win[a][b] = (r >= 0 && c >= 0) ? __ldg(&x[r * IMG_W + c]) : 0.0f;
        }
    }

    #pragma unroll
    for (int step = 0; step < PW; step++) {
        const int row = r0 + step;
        float acc = 0.0f;
        #pragma unroll
        for (int a = 0; a < PW; a++)
            #pragma unroll
            for (int b = 0; b < PW; b++)
                acc += fabsf(p[a * PW + b] - win[a][b]);
        const float f = 1.0f - acc * (1.0f / 49.0f);
        g_F[(k * NR + row) * IMG_W + j] = (f > thr) ? f : 0.0f;

        if (step < PW - 1) {
            #pragma unroll
            for (int a = 0; a < PW - 1; a++)
                #pragma unroll
                for (int b = 0; b < PW; b++)
                    win[a][b] = win[a + 1][b];
            #pragma unroll
            for (int b = 0; b < PW; b++) {
                const int c = j - PW + b;           // row 'row' is always >= 0
                win[PW - 1][b] = (c >= 0) ? __ldg(&x[row * IMG_W + c]) : 0.0f;
            }
        }
    }
}

// ---------------------------------------------------------------------------
// Kernel B: 144 blocks = 48 column-tiles x 3 class-splits (~1 per SM).
// Stage F[224 x 32] into smem (128B rows, LDS.128-friendly). Thread =
// (class-group, col-quad): per tap LDG.64 meta (8-lane broadcast) + LDS.128
// + 4 FFMA. Block max -> atomicMax; last of 144 blocks writes out.
// ---------------------------------------------------------------------------
__global__ void __launch_bounds__(384) geneo3_kernel(float* __restrict__ out) {
    __shared__ __align__(16) float sF[NROWS * TC];
    __shared__ float smax[12];
    const int tid   = threadIdx.x;
    const int split = blockIdx.x % NSPLIT;
    const int j0    = (blockIdx.x / NSPLIT) * TC;

    // Stage: 224 rows x 32 cols, float4 granularity (1792 quads / 384 thr).
    for (int e = tid; e < NROWS * (TC / 4); e += 384) {
        const int row = e >> 3;
        const int q   = e & 7;
        ((float4*)sF)[row * (TC / 4) + q] =
            *(const float4*)&g_F[row * IMG_W + j0 + q * 4];
    }
    __syncthreads();

    const int count = __ldg(&g_icount);
    const int lane8 = tid & 7;                 // col-quad within class
    const int cgrp  = tid >> 3;                // 0..47
    float m = -3.0e38f;

    #pragma unroll
    for (int it = 0; it < NIT; it++) {
        const int cls = split + NSPLIT * (cgrp + NGRP * it);
        if (cls < count) {
            const int2* tp = &g_tap[cls * 32];
            float4 acc = make_float4(0.f, 0.f, 0.f, 0.f);
            #pragma unroll
            for (int t = 0; t < 32; t++) {
                const int2  mt = __ldg(&tp[t]);
                const float w  = __int_as_float(mt.y);
                const float4 v = ((const float4*)sF)[mt.x * (TC / 4) + lane8];
                acc.x = fmaf(w, v.x, acc.x);
                acc.y = fmaf(w, v.y, acc.y);
                acc.z = fmaf(w, v.z, acc.z);
                acc.w = fmaf(w, v.w, acc.w);
            }
            m = fmaxf(m, fmaxf(fmaxf(acc.x, acc.y), fmaxf(acc.z, acc.w)));
        }
    }

    #pragma unroll
    for (int o = 16; o > 0; o >>= 1)
        m = fmaxf(m, __shfl_xor_sync(0xffffffffu, m, o));
    if ((tid & 31) == 0) smax[tid >> 5] = m;
    __syncthreads();
    if (tid == 0) {
        #pragma unroll
        for (int w = 1; w < 12; w++) m = fmaxf(m, smax[w]);
        atomicMax(&g_enc, enc_f(m));
        __threadfence();
        const unsigned old = atomicAdd(&g_done, 1u);
        if (old == (unsigned)(NBLK3 - 1)) {
            const unsigned u = atomicOr(&g_enc, 0u);   // coherent read
            out[0] = dec_f(u) * (1.0f / 7.0f);
        }
    }
}

extern "C" void kernel_launch(void* const* d_in, const int* in_sizes, int n_in,
                              void* d_out, int out_size) {
    const float* x        = (const float*)d_in[0];
    const float* patterns = (const float*)d_in[1];
    const float* vectors  = (const float*)d_in[2];
    float* out = (float*)d_out;

    geneo1_kernel<<<NBLK1 + 1, BS1>>>(x, patterns, vectors);
    geneo3_kernel<<<NBLK3, 384>>>(out);
}